// round 7
// baseline (speedup 1.0000x reference)
#include <cuda_runtime.h>
#include <cuda_bf16.h>
#include <cstdint>

// ============================================================================
// Problem constants
// ============================================================================
#define N_ATOMS   32768
#define N_SPECIES 4
#define N_FEAT    7584
#define N_FEAT_P  7616      // padded to multiple of KC
#define HIDDEN    256

#define MT       128        // CTA rows
#define NTILE    128        // CTA cols
#define KC       64         // k-chunk per stage
#define NTHREADS 256
#define TOTCH    (N_FEAT_P / KC)   // 119
#define NCH0     60                // split-K slice 0 chunks (slice 1: 59)

// smem geometry: rows of 64 bf16 = 128B data + 16B pad -> conflict-free ldmatrix
#define RSTRIDE     144
#define PLANE_BYTES (128 * RSTRIDE)      // 18432
#define SOFF_AH     0
#define SOFF_AL     (PLANE_BYTES)
#define SOFF_BH     (2 * PLANE_BYTES)
#define SOFF_BL     (3 * PLANE_BYTES)
#define STAGE_BYTES (4 * PLANE_BYTES)    // 73728
#define NSTAGE      3
#define OFF_BIAS    (NSTAGE * STAGE_BYTES)   // 221184
#define SMEM_DYN    (OFF_BIAS + 512)         // 221696

// ============================================================================
// Device scratch (allocation-free)
// ============================================================================
__device__ __align__(16) __nv_bfloat16 g_W1h[(size_t)N_SPECIES * HIDDEN * N_FEAT_P];
__device__ __align__(16) __nv_bfloat16 g_W1l[(size_t)N_SPECIES * HIDDEN * N_FEAT_P];
__device__ __align__(16) __nv_bfloat16 g_W2h[N_SPECIES * HIDDEN * HIDDEN];
__device__ __align__(16) __nv_bfloat16 g_W2l[N_SPECIES * HIDDEN * HIDDEN];
__device__ __align__(16) __nv_bfloat16 g_W3h[N_SPECIES * HIDDEN * HIDDEN];
__device__ __align__(16) __nv_bfloat16 g_W3l[N_SPECIES * HIDDEN * HIDDEN];
__device__ __align__(16) __nv_bfloat16 g_H1h[(size_t)N_ATOMS * HIDDEN];
__device__ __align__(16) __nv_bfloat16 g_H1l[(size_t)N_ATOMS * HIDDEN];
__device__ __align__(16) __nv_bfloat16 g_H2h[(size_t)N_ATOMS * HIDDEN];
__device__ __align__(16) __nv_bfloat16 g_H2l[(size_t)N_ATOMS * HIDDEN];
__device__ __align__(16) float         g_P[(size_t)2 * N_ATOMS * HIDDEN];  // split-K partials

// ============================================================================
// Baseline-PTX primitives
// ============================================================================
__device__ __forceinline__ void cp16(uint32_t s, const void* g) {
    asm volatile("cp.async.cg.shared.global [%0], [%1], 16;\n" :: "r"(s), "l"(g));
}
__device__ __forceinline__ void cp_commit() {
    asm volatile("cp.async.commit_group;\n" ::: "memory");
}
template<int N> __device__ __forceinline__ void cp_wait() {
    asm volatile("cp.async.wait_group %0;\n" :: "n"(N) : "memory");
}
__device__ __forceinline__ void ldsm4(uint32_t& r0, uint32_t& r1, uint32_t& r2,
                                      uint32_t& r3, uint32_t a) {
    asm volatile("ldmatrix.sync.aligned.m8n8.x4.shared.b16 {%0,%1,%2,%3}, [%4];\n"
                 : "=r"(r0), "=r"(r1), "=r"(r2), "=r"(r3) : "r"(a));
}
__device__ __forceinline__ void mma16816(float* c, const uint32_t* a, const uint32_t* b) {
    asm volatile(
        "mma.sync.aligned.m16n8k16.row.col.f32.bf16.bf16.f32 "
        "{%0,%1,%2,%3}, {%4,%5,%6,%7}, {%8,%9}, {%0,%1,%2,%3};\n"
        : "+f"(c[0]), "+f"(c[1]), "+f"(c[2]), "+f"(c[3])
        : "r"(a[0]), "r"(a[1]), "r"(a[2]), "r"(a[3]), "r"(b[0]), "r"(b[1]));
}
__device__ __forceinline__ uint32_t pk(__nv_bfloat16 a, __nv_bfloat16 b) {
    __nv_bfloat162 t; t.x = a; t.y = b;
    return *(uint32_t*)&t;
}

// Fragment set for one k16 step
struct Frag {
    uint32_t ah[2][4], al[2][4];
    uint32_t bh[8][2], bl[8][2];
};

// ============================================================================
// Stage loaders
// ============================================================================
// B planes: first/second half split so cp issue can be spread across k-steps
template<int HALF>  // 0: hi plane, 1: lo plane
__device__ __forceinline__ void cp_B_half(uint32_t st, const __nv_bfloat16* Bh0,
                                          const __nv_bfloat16* Bl0, int ldb, int k0, int tid) {
#pragma unroll
    for (int i = 0; i < 4; ++i) {
        int jj = (tid + i * NTHREADS) & 1023;
        int n = jj >> 3, seg = jj & 7;
        const __nv_bfloat16* src = (HALF == 0 ? Bh0 : Bl0) + (size_t)n * ldb + k0 + seg * 8;
        uint32_t dst = st + (HALF == 0 ? SOFF_BH : SOFF_BL) + n * RSTRIDE + seg * 16;
        cp16(dst, src);
    }
}
template<int HALF>
__device__ __forceinline__ void cp_A_half(uint32_t st, const __nv_bfloat16* Ah0,
                                          const __nv_bfloat16* Al0, int k0, int tid) {
#pragma unroll
    for (int i = 0; i < 4; ++i) {
        int jj = (tid + i * NTHREADS) & 1023;
        int m = jj >> 3, seg = jj & 7;
        const __nv_bfloat16* src = (HALF == 0 ? Ah0 : Al0) + (size_t)m * HIDDEN + k0 + seg * 8;
        uint32_t dst = st + (HALF == 0 ? SOFF_AH : SOFF_AL) + m * RSTRIDE + seg * 16;
        cp16(dst, src);
    }
}
// A fp32 (features): register-staged LDG; Klim = valid k count (rest zero)
__device__ __forceinline__ void ldg_A(float4 v[8], const float* Abase, int k0, int tid,
                                      int Klim) {
#pragma unroll
    for (int i = 0; i < 8; ++i) {
        int j = tid + i * NTHREADS;
        int r = j >> 4, q = j & 15;
        int kg = k0 + q * 4;
        if (kg < Klim) v[i] = *(const float4*)(Abase + (size_t)r * N_FEAT + kg);
        else           v[i] = make_float4(0.f, 0.f, 0.f, 0.f);
    }
}
// convert + store to hi/lo smem planes; HALF 0: first 4 vecs, 1: last 4
template<int HALF>
__device__ __forceinline__ void sts_A_half(const float4 v[8], char* sm, uint32_t stOff,
                                           int tid) {
#pragma unroll
    for (int i = HALF * 4; i < HALF * 4 + 4; ++i) {
        int j = tid + i * NTHREADS;
        int r = j >> 4, q = j & 15;
        float4 x = v[i];
        __nv_bfloat16 h0 = __float2bfloat16(x.x), h1 = __float2bfloat16(x.y);
        __nv_bfloat16 h2 = __float2bfloat16(x.z), h3 = __float2bfloat16(x.w);
        uint2 hp, lp;
        hp.x = pk(h0, h1); hp.y = pk(h2, h3);
        lp.x = pk(__float2bfloat16(x.x - __bfloat162float(h0)),
                  __float2bfloat16(x.y - __bfloat162float(h1)));
        lp.y = pk(__float2bfloat16(x.z - __bfloat162float(h2)),
                  __float2bfloat16(x.w - __bfloat162float(h3)));
        *(uint2*)(sm + stOff + SOFF_AH + r * RSTRIDE + q * 8) = hp;
        *(uint2*)(sm + stOff + SOFF_AL + r * RSTRIDE + q * 8) = lp;
    }
}

// ============================================================================
// Fragment load (k-step ks from stage st) and MMA on a loaded fragment set
// ============================================================================
__device__ __forceinline__ void ldsm_step(uint32_t st, int ks, Frag& f,
                                          const uint32_t aOff[2], const uint32_t bOff[4]) {
#pragma unroll
    for (int mt = 0; mt < 2; ++mt) {
        ldsm4(f.ah[mt][0], f.ah[mt][1], f.ah[mt][2], f.ah[mt][3], st + aOff[mt] + ks * 32);
        ldsm4(f.al[mt][0], f.al[mt][1], f.al[mt][2], f.al[mt][3],
              st + aOff[mt] + PLANE_BYTES + ks * 32);
    }
#pragma unroll
    for (int ng = 0; ng < 4; ++ng) {
        ldsm4(f.bh[2 * ng][0], f.bh[2 * ng][1], f.bh[2 * ng + 1][0], f.bh[2 * ng + 1][1],
              st + bOff[ng] + ks * 32);
        ldsm4(f.bl[2 * ng][0], f.bl[2 * ng][1], f.bl[2 * ng + 1][0], f.bl[2 * ng + 1][1],
              st + bOff[ng] + PLANE_BYTES + ks * 32);
    }
}
__device__ __forceinline__ void mma_step(float acc[2][8][4], const Frag& f) {
#pragma unroll
    for (int mt = 0; mt < 2; ++mt)
#pragma unroll
        for (int nt = 0; nt < 8; ++nt) {
            mma16816(acc[mt][nt], f.ah[mt], f.bh[nt]);
            mma16816(acc[mt][nt], f.al[mt], f.bh[nt]);
            mma16816(acc[mt][nt], f.ah[mt], f.bl[nt]);
        }
}

// ============================================================================
// Main GEMM.  D[m,n] = sum_k A[m,k]*B[n,k]
//   SPLIT: write fp32 partials to Pout; else fused bias+silu+hi/lo split
// ============================================================================
template<bool AFP32, bool SPLIT>
__global__ void __launch_bounds__(NTHREADS, 1)
gemm_main(const float* __restrict__ Afp,
          const __nv_bfloat16* __restrict__ Ahg, const __nv_bfloat16* __restrict__ Alg,
          int nchA, int nchTot,
          const __nv_bfloat16* __restrict__ Bhg, const __nv_bfloat16* __restrict__ Blg,
          int ldb,
          const float* __restrict__ bias,
          __nv_bfloat16* __restrict__ Oh, __nv_bfloat16* __restrict__ Ol,
          float* __restrict__ Pout)
{
    extern __shared__ char sm[];
    const uint32_t sb = (uint32_t)__cvta_generic_to_shared(sm);
    const int tid = threadIdx.x;
    const int nblk = blockIdx.x;
    const int row0 = blockIdx.y * MT;
    const int s = row0 >> 13;               // 8192 atoms / species
    const int z = SPLIT ? blockIdx.z : 0;
    const int kbase = (SPLIT && z) ? nchA * KC : 0;
    const int nch = SPLIT ? (z ? nchTot - nchA : nchA) : nchA;
    const int Klim = AFP32 ? (N_FEAT - kbase) : 0x7fffffff;

    const __nv_bfloat16* Bh0 = Bhg + ((size_t)s * HIDDEN + nblk * NTILE) * ldb + kbase;
    const __nv_bfloat16* Bl0 = Blg + ((size_t)s * HIDDEN + nblk * NTILE) * ldb + kbase;
    const float* Abase = AFP32 ? (Afp + (size_t)row0 * N_FEAT + kbase) : nullptr;
    const __nv_bfloat16* Ah0 = AFP32 ? nullptr : (Ahg + (size_t)row0 * HIDDEN);
    const __nv_bfloat16* Al0 = AFP32 ? nullptr : (Alg + (size_t)row0 * HIDDEN);

    float* sbias = (float*)(sm + OFF_BIAS);
    if (!SPLIT && tid < NTILE) sbias[tid] = bias[s * HIDDEN + nblk * NTILE + tid];

    // ---- prologue: fill stages 0 and 1 ----
    float4 av[8];
    if (AFP32) ldg_A(av, Abase, 0, tid, Klim);
    cp_B_half<0>(sb, Bh0, Bl0, ldb, 0, tid);
    cp_B_half<1>(sb, Bh0, Bl0, ldb, 0, tid);
    if (!AFP32) { cp_A_half<0>(sb, Ah0, Al0, 0, tid); cp_A_half<1>(sb, Ah0, Al0, 0, tid); }
    cp_commit();
    cp_B_half<0>(sb + STAGE_BYTES, Bh0, Bl0, ldb, KC, tid);
    cp_B_half<1>(sb + STAGE_BYTES, Bh0, Bl0, ldb, KC, tid);
    if (!AFP32) {
        cp_A_half<0>(sb + STAGE_BYTES, Ah0, Al0, KC, tid);
        cp_A_half<1>(sb + STAGE_BYTES, Ah0, Al0, KC, tid);
    }
    cp_commit();
    if (AFP32) {
        sts_A_half<0>(av, sm, 0, tid);
        sts_A_half<1>(av, sm, 0, tid);
        ldg_A(av, Abase, KC, tid, Klim);    // av = chunk 1
    }

    // ---- per-warp fragment addressing ----
    const int lane = tid & 31, wid = tid >> 5;
    const int warpM = wid & 3, warpN = wid >> 2;
    const int m0 = warpM * 32, n0 = warpN * 64;
    const int lr = lane & 15, lcb = (lane >> 4) * 16;
    uint32_t aOff[2], bOff[4];
#pragma unroll
    for (int mt = 0; mt < 2; ++mt)
        aOff[mt] = SOFF_AH + (uint32_t)(m0 + mt * 16 + lr) * RSTRIDE + lcb;
    const int brow = (lane & 7) + ((lane & 16) >> 1);
    const int bcb = (lane & 8) * 2;
#pragma unroll
    for (int ng = 0; ng < 4; ++ng)
        bOff[ng] = SOFF_BH + (uint32_t)(n0 + ng * 16 + brow) * RSTRIDE + bcb;

    float acc[2][8][4];
#pragma unroll
    for (int mt = 0; mt < 2; ++mt)
#pragma unroll
        for (int nt = 0; nt < 8; ++nt)
#pragma unroll
            for (int q = 0; q < 4; ++q) acc[mt][nt][q] = 0.f;

    // ---- main loop: 3-stage ring, fragment double-buffer inside chunk ----
    Frag fA, fB;
    uint32_t st0 = 0, st1 = STAGE_BYTES, st2 = 2 * STAGE_BYTES;
    for (int c = 0; c < nch; ++c) {
        if (c + 1 < nch) { cp_wait<1>(); } else { cp_wait<0>(); }
        __syncthreads();
        const uint32_t cur = sb + st0;
        const bool pf = (c + 2 < nch);

        // ks0 fragments (exposed once per chunk)
        ldsm_step(cur, 0, fA, aOff, bOff);

        // ks1 prefetch + spread cp for stage c+2 + mma(ks0)
        ldsm_step(cur, 1, fB, aOff, bOff);
        if (pf) cp_B_half<0>(sb + st2, Bh0, Bl0, ldb, (c + 2) * KC, tid);
        mma_step(acc, fA);

        // ks2 prefetch + more cp + mma(ks1)
        ldsm_step(cur, 2, fA, aOff, bOff);
        if (pf) {
            cp_B_half<1>(sb + st2, Bh0, Bl0, ldb, (c + 2) * KC, tid);
            if (!AFP32) {
                cp_A_half<0>(sb + st2, Ah0, Al0, (c + 2) * KC, tid);
                cp_A_half<1>(sb + st2, Ah0, Al0, (c + 2) * KC, tid);
            }
            cp_commit();
        }
        mma_step(acc, fB);

        // ks3 prefetch + A split-store for chunk c+1 + mma(ks2)
        ldsm_step(cur, 3, fB, aOff, bOff);
        if (AFP32 && c + 1 < nch) {
            sts_A_half<0>(av, sm, st1, tid);
            sts_A_half<1>(av, sm, st1, tid);
        }
        mma_step(acc, fA);

        if (AFP32 && pf) ldg_A(av, Abase, (c + 2) * KC, tid, Klim);
        mma_step(acc, fB);

        uint32_t t = st0; st0 = st1; st1 = st2; st2 = t;
    }

    // ---- epilogue ----
    if (SPLIT) {
        float* P = Pout + (size_t)z * N_ATOMS * HIDDEN;
#pragma unroll
        for (int mt = 0; mt < 2; ++mt)
#pragma unroll
            for (int nt = 0; nt < 8; ++nt) {
                const int rg = row0 + m0 + mt * 16 + (lane >> 2);
                const int cg = nblk * NTILE + n0 + nt * 8 + (lane & 3) * 2;
                float2 v0 = make_float2(acc[mt][nt][0], acc[mt][nt][1]);
                float2 v1 = make_float2(acc[mt][nt][2], acc[mt][nt][3]);
                *(float2*)(P + (size_t)rg * HIDDEN + cg) = v0;
                *(float2*)(P + (size_t)(rg + 8) * HIDDEN + cg) = v1;
            }
    } else {
#pragma unroll
        for (int mt = 0; mt < 2; ++mt)
#pragma unroll
            for (int nt = 0; nt < 8; ++nt) {
                const int rg = row0 + m0 + mt * 16 + (lane >> 2);
                const int cl = n0 + nt * 8 + (lane & 3) * 2;
                const int cg = nblk * NTILE + cl;
                const float b0 = sbias[cl], b1 = sbias[cl + 1];
                float v[4];
                v[0] = acc[mt][nt][0] + b0; v[1] = acc[mt][nt][1] + b1;
                v[2] = acc[mt][nt][2] + b0; v[3] = acc[mt][nt][3] + b1;
#pragma unroll
                for (int q = 0; q < 4; ++q) v[q] = v[q] / (1.f + __expf(-v[q]));
                __nv_bfloat16 h0 = __float2bfloat16(v[0]), h1 = __float2bfloat16(v[1]);
                __nv_bfloat16 h2 = __float2bfloat16(v[2]), h3 = __float2bfloat16(v[3]);
                uint32_t hi0 = pk(h0, h1), hi1 = pk(h2, h3);
                uint32_t lo0 = pk(__float2bfloat16(v[0] - __bfloat162float(h0)),
                                  __float2bfloat16(v[1] - __bfloat162float(h1)));
                uint32_t lo1 = pk(__float2bfloat16(v[2] - __bfloat162float(h2)),
                                  __float2bfloat16(v[3] - __bfloat162float(h3)));
                *(uint32_t*)(Oh + (size_t)rg * HIDDEN + cg) = hi0;
                *(uint32_t*)(Ol + (size_t)rg * HIDDEN + cg) = lo0;
                *(uint32_t*)(Oh + (size_t)(rg + 8) * HIDDEN + cg) = hi1;
                *(uint32_t*)(Ol + (size_t)(rg + 8) * HIDDEN + cg) = lo1;
            }
    }
}

// ============================================================================
// Split-K combine: P0 + P1 + bias -> silu -> bf16 hi/lo planes
// ============================================================================
__global__ void __launch_bounds__(256)
combine_silu(const float* __restrict__ P, const float* __restrict__ bias,
             __nv_bfloat16* __restrict__ Oh, __nv_bfloat16* __restrict__ Ol)
{
    const size_t i4 = ((size_t)blockIdx.x * 256 + threadIdx.x) * 4;
    const int row = (int)(i4 >> 8);
    const int col = (int)(i4 & 255);
    const int s = row >> 13;
    float4 a = *(const float4*)(P + i4);
    float4 b = *(const float4*)(P + (size_t)N_ATOMS * HIDDEN + i4);
    const float* bp = bias + s * HIDDEN + col;
    float v[4] = {a.x + b.x + bp[0], a.y + b.y + bp[1],
                  a.z + b.z + bp[2], a.w + b.w + bp[3]};
#pragma unroll
    for (int q = 0; q < 4; ++q) v[q] = v[q] / (1.f + __expf(-v[q]));
    __nv_bfloat16 h0 = __float2bfloat16(v[0]), h1 = __float2bfloat16(v[1]);
    __nv_bfloat16 h2 = __float2bfloat16(v[2]), h3 = __float2bfloat16(v[3]);
    uint2 hp, lp;
    hp.x = pk(h0, h1); hp.y = pk(h2, h3);
    lp.x = pk(__float2bfloat16(v[0] - __bfloat162float(h0)),
              __float2bfloat16(v[1] - __bfloat162float(h1)));
    lp.y = pk(__float2bfloat16(v[2] - __bfloat162float(h2)),
              __float2bfloat16(v[3] - __bfloat162float(h3)));
    *(uint2*)(Oh + i4) = hp;
    *(uint2*)(Ol + i4) = lp;
}

// ============================================================================
// Weight transpose + bf16 hi/lo split:  W[s][f][h] -> Wt[s][h][fp]
// ============================================================================
__global__ void transpose_split(const float* __restrict__ W,
                                __nv_bfloat16* __restrict__ Th,
                                __nv_bfloat16* __restrict__ Tl,
                                int F, int Fp, int H)
{
    __shared__ float t[32][33];
    const int s = blockIdx.z;
    const int f0 = blockIdx.x * 32, h0 = blockIdx.y * 32;
    const float* Ws = W + (size_t)s * F * H;
#pragma unroll
    for (int i = threadIdx.y; i < 32; i += 8) {
        int f = f0 + i, h = h0 + threadIdx.x;
        t[i][threadIdx.x] = (f < F) ? Ws[(size_t)f * H + h] : 0.f;
    }
    __syncthreads();
    __nv_bfloat16* Ths = Th + (size_t)s * H * Fp;
    __nv_bfloat16* Tls = Tl + (size_t)s * H * Fp;
#pragma unroll
    for (int i = threadIdx.y; i < 32; i += 8) {
        int h = h0 + i, f = f0 + threadIdx.x;
        float v = t[threadIdx.x][i];
        __nv_bfloat16 hi = __float2bfloat16(v);
        float lo = v - __bfloat162float(hi);
        Ths[(size_t)h * Fp + f] = hi;
        Tls[(size_t)h * Fp + f] = __float2bfloat16(lo);
    }
}

// ============================================================================
// Output zero + final layer-4 dot + segment scatter-add
// ============================================================================
__global__ void zero_out(float* out, int n) {
    int i = blockIdx.x * blockDim.x + threadIdx.x;
    if (i < n) out[i] = 0.f;
}

__global__ void __launch_bounds__(256)
layer4_reduce(const __nv_bfloat16* __restrict__ Hh,
              const __nv_bfloat16* __restrict__ Hl,
              const float* __restrict__ W4, const float* __restrict__ b4,
              const int* __restrict__ sidx, float* __restrict__ out)
{
    __shared__ float w[HIDDEN];
    const int atom = blockIdx.x * 256 + threadIdx.x;
    const int s = atom >> 13;
    w[threadIdx.x] = W4[s * HIDDEN + threadIdx.x];
    __syncthreads();

    const uint4* ph = (const uint4*)(Hh + (size_t)atom * HIDDEN);
    const uint4* pl = (const uint4*)(Hl + (size_t)atom * HIDDEN);
    float e = b4[s];
#pragma unroll 8
    for (int i = 0; i < 32; ++i) {
        uint4 a = ph[i];
        uint4 c = pl[i];
        const uint32_t* ap = &a.x;
        const uint32_t* cp = &c.x;
#pragma unroll
        for (int j = 0; j < 4; ++j) {
            __nv_bfloat162 hv = *(__nv_bfloat162*)&ap[j];
            __nv_bfloat162 lv = *(__nv_bfloat162*)&cp[j];
            int col = i * 8 + j * 2;
            e += (__bfloat162float(hv.x) + __bfloat162float(lv.x)) * w[col];
            e += (__bfloat162float(hv.y) + __bfloat162float(lv.y)) * w[col + 1];
        }
    }
    atomicAdd(out + sidx[atom], e);
}

// ============================================================================
// Host launcher
// ============================================================================
extern "C" void kernel_launch(void* const* d_in, const int* in_sizes, int n_in,
                              void* d_out, int out_size)
{
    int o = 0;
    const float* feat = (const float*)d_in[o++];
    const int* sidx = (const int*)d_in[o++];
    if (o < n_in && in_sizes[o] == 1) o++;  // n_structures scalar, if present
    const float* W1 = (const float*)d_in[o++];
    const float* b1 = (const float*)d_in[o++];
    const float* W2 = (const float*)d_in[o++];
    const float* b2 = (const float*)d_in[o++];
    const float* W3 = (const float*)d_in[o++];
    const float* b3 = (const float*)d_in[o++];
    const float* W4 = (const float*)d_in[o++];
    const float* b4 = (const float*)d_in[o++];

    __nv_bfloat16 *w1h, *w1l, *w2h, *w2l, *w3h, *w3l, *h1h, *h1l, *h2h, *h2l;
    float* pbuf;
    cudaGetSymbolAddress((void**)&w1h, g_W1h);
    cudaGetSymbolAddress((void**)&w1l, g_W1l);
    cudaGetSymbolAddress((void**)&w2h, g_W2h);
    cudaGetSymbolAddress((void**)&w2l, g_W2l);
    cudaGetSymbolAddress((void**)&w3h, g_W3h);
    cudaGetSymbolAddress((void**)&w3l, g_W3l);
    cudaGetSymbolAddress((void**)&h1h, g_H1h);
    cudaGetSymbolAddress((void**)&h1l, g_H1l);
    cudaGetSymbolAddress((void**)&h2h, g_H2h);
    cudaGetSymbolAddress((void**)&h2l, g_H2l);
    cudaGetSymbolAddress((void**)&pbuf, g_P);

    cudaFuncSetAttribute(gemm_main<true, true>,
                         cudaFuncAttributeMaxDynamicSharedMemorySize, SMEM_DYN);
    cudaFuncSetAttribute(gemm_main<false, false>,
                         cudaFuncAttributeMaxDynamicSharedMemorySize, SMEM_DYN);

    // Prep: transpose + hi/lo split weights (K-major, zero-padded to N_FEAT_P)
    transpose_split<<<dim3(N_FEAT_P / 32, HIDDEN / 32, N_SPECIES), dim3(32, 8)>>>(
        W1, w1h, w1l, N_FEAT, N_FEAT_P, HIDDEN);
    transpose_split<<<dim3(HIDDEN / 32, HIDDEN / 32, N_SPECIES), dim3(32, 8)>>>(
        W2, w2h, w2l, HIDDEN, HIDDEN, HIDDEN);
    transpose_split<<<dim3(HIDDEN / 32, HIDDEN / 32, N_SPECIES), dim3(32, 8)>>>(
        W3, w3h, w3l, HIDDEN, HIDDEN, HIDDEN);

    // Layer 1: split-K x2 -> fp32 partials -> combine(bias+silu+split)
    gemm_main<true, true><<<dim3(HIDDEN / NTILE, N_ATOMS / MT, 2), NTHREADS, SMEM_DYN>>>(
        feat, nullptr, nullptr, NCH0, TOTCH,
        w1h, w1l, N_FEAT_P, nullptr, nullptr, nullptr, pbuf);
    combine_silu<<<(N_ATOMS * HIDDEN) / (256 * 4), 256>>>(pbuf, b1, h1h, h1l);

    const dim3 grid2(HIDDEN / NTILE, N_ATOMS / MT);

    // Layer 2: A = H1 planes (K = 256, 4 chunks)
    gemm_main<false, false><<<grid2, NTHREADS, SMEM_DYN>>>(
        nullptr, h1h, h1l, HIDDEN / KC, HIDDEN / KC,
        w2h, w2l, HIDDEN, b2, h2h, h2l, nullptr);

    // Layer 3: A = H2 planes -> H1
    gemm_main<false, false><<<grid2, NTHREADS, SMEM_DYN>>>(
        nullptr, h2h, h2l, HIDDEN / KC, HIDDEN / KC,
        w3h, w3l, HIDDEN, b3, h1h, h1l, nullptr);

    // Layer 4 + segment sum
    zero_out<<<(out_size + 255) / 256, 256>>>((float*)d_out, out_size);
    layer4_reduce<<<N_ATOMS / 256, 256>>>(h1h, h1l, W4, b4, sidx, (float*)d_out);
}

// round 8
// speedup vs baseline: 1.0572x; 1.0572x over previous
#include <cuda_runtime.h>
#include <cuda_bf16.h>
#include <cstdint>

// ============================================================================
// Problem constants
// ============================================================================
#define N_ATOMS   32768
#define N_SPECIES 4
#define N_FEAT    7584
#define N_FEAT_P  7616      // padded to multiple of KC
#define HIDDEN    256

#define MT       128        // CTA rows
#define NTILE    128        // CTA cols
#define KC       64         // k-chunk per stage
#define NTHREADS 512        // 16 warps, 32x32 warp tiles (4 warps/SMSP)
#define TOTCH    (N_FEAT_P / KC)   // 119
#define NCH0     60                // split-K slice 0 chunks (slice 1: 59)

// smem geometry: rows of 64 bf16 = 128B data + 16B pad -> conflict-free ldmatrix
#define RSTRIDE     144
#define PLANE_BYTES (128 * RSTRIDE)      // 18432
#define SOFF_AH     0
#define SOFF_AL     (PLANE_BYTES)
#define SOFF_BH     (2 * PLANE_BYTES)
#define SOFF_BL     (3 * PLANE_BYTES)
#define STAGE_BYTES (4 * PLANE_BYTES)    // 73728
#define NSTAGE      3
#define OFF_BIAS    (NSTAGE * STAGE_BYTES)   // 221184
#define SMEM_DYN    (OFF_BIAS + 512)         // 221696

// ============================================================================
// Device scratch (allocation-free)
// ============================================================================
__device__ __align__(16) __nv_bfloat16 g_W1h[(size_t)N_SPECIES * HIDDEN * N_FEAT_P];
__device__ __align__(16) __nv_bfloat16 g_W1l[(size_t)N_SPECIES * HIDDEN * N_FEAT_P];
__device__ __align__(16) __nv_bfloat16 g_W2h[N_SPECIES * HIDDEN * HIDDEN];
__device__ __align__(16) __nv_bfloat16 g_W2l[N_SPECIES * HIDDEN * HIDDEN];
__device__ __align__(16) __nv_bfloat16 g_W3h[N_SPECIES * HIDDEN * HIDDEN];
__device__ __align__(16) __nv_bfloat16 g_W3l[N_SPECIES * HIDDEN * HIDDEN];
__device__ __align__(16) __nv_bfloat16 g_H1h[(size_t)N_ATOMS * HIDDEN];
__device__ __align__(16) __nv_bfloat16 g_H1l[(size_t)N_ATOMS * HIDDEN];
__device__ __align__(16) __nv_bfloat16 g_H2h[(size_t)N_ATOMS * HIDDEN];
__device__ __align__(16) __nv_bfloat16 g_H2l[(size_t)N_ATOMS * HIDDEN];
__device__ __align__(16) float         g_P[(size_t)2 * N_ATOMS * HIDDEN];  // split-K partials

// ============================================================================
// Baseline-PTX primitives
// ============================================================================
__device__ __forceinline__ void cp16(uint32_t s, const void* g) {
    asm volatile("cp.async.cg.shared.global [%0], [%1], 16;\n" :: "r"(s), "l"(g));
}
__device__ __forceinline__ void cp_commit() {
    asm volatile("cp.async.commit_group;\n" ::: "memory");
}
template<int N> __device__ __forceinline__ void cp_wait() {
    asm volatile("cp.async.wait_group %0;\n" :: "n"(N) : "memory");
}
__device__ __forceinline__ void ldsm4(uint32_t& r0, uint32_t& r1, uint32_t& r2,
                                      uint32_t& r3, uint32_t a) {
    asm volatile("ldmatrix.sync.aligned.m8n8.x4.shared.b16 {%0,%1,%2,%3}, [%4];\n"
                 : "=r"(r0), "=r"(r1), "=r"(r2), "=r"(r3) : "r"(a));
}
__device__ __forceinline__ void mma16816(float* c, const uint32_t* a, const uint32_t* b) {
    asm volatile(
        "mma.sync.aligned.m16n8k16.row.col.f32.bf16.bf16.f32 "
        "{%0,%1,%2,%3}, {%4,%5,%6,%7}, {%8,%9}, {%0,%1,%2,%3};\n"
        : "+f"(c[0]), "+f"(c[1]), "+f"(c[2]), "+f"(c[3])
        : "r"(a[0]), "r"(a[1]), "r"(a[2]), "r"(a[3]), "r"(b[0]), "r"(b[1]));
}
__device__ __forceinline__ uint32_t pk(__nv_bfloat16 a, __nv_bfloat16 b) {
    __nv_bfloat162 t; t.x = a; t.y = b;
    return *(uint32_t*)&t;
}

// Fragment set for one k16 step (32x32 warp tile)
struct Frag {
    uint32_t ah[2][4], al[2][4];   // 2 m16 tiles, hi/lo planes
    uint32_t bh[4][2], bl[4][2];   // 4 n8 tiles, hi/lo planes
};

// ============================================================================
// Stage loaders (512 threads)
// ============================================================================
// B plane half: HALF 0 = hi plane, 1 = lo plane. 1024 cp16 per plane -> 2/thread
template<int HALF>
__device__ __forceinline__ void cp_B_half(uint32_t st, const __nv_bfloat16* Bh0,
                                          const __nv_bfloat16* Bl0, int ldb, int k0, int tid) {
#pragma unroll
    for (int i = 0; i < 2; ++i) {
        int jj = tid + i * NTHREADS;           // 0..1023
        int n = jj >> 3, seg = jj & 7;
        const __nv_bfloat16* src = (HALF == 0 ? Bh0 : Bl0) + (size_t)n * ldb + k0 + seg * 8;
        uint32_t dst = st + (HALF == 0 ? SOFF_BH : SOFF_BL) + n * RSTRIDE + seg * 16;
        cp16(dst, src);
    }
}
template<int HALF>
__device__ __forceinline__ void cp_A_half(uint32_t st, const __nv_bfloat16* Ah0,
                                          const __nv_bfloat16* Al0, int k0, int tid) {
#pragma unroll
    for (int i = 0; i < 2; ++i) {
        int jj = tid + i * NTHREADS;
        int m = jj >> 3, seg = jj & 7;
        const __nv_bfloat16* src = (HALF == 0 ? Ah0 : Al0) + (size_t)m * HIDDEN + k0 + seg * 8;
        uint32_t dst = st + (HALF == 0 ? SOFF_AH : SOFF_AL) + m * RSTRIDE + seg * 16;
        cp16(dst, src);
    }
}
// A fp32 (features): 2048 float4 per chunk -> 4/thread, split in halves of 2
template<int HALF>
__device__ __forceinline__ void ldg_A_half(float4 av[4], const float* Abase, int k0,
                                           int tid, int Klim) {
#pragma unroll
    for (int i = 2 * HALF; i < 2 * HALF + 2; ++i) {
        int j = tid + i * NTHREADS;
        int r = j >> 4, q = j & 15;
        int kg = k0 + q * 4;
        if (kg < Klim) av[i] = *(const float4*)(Abase + (size_t)r * N_FEAT + kg);
        else           av[i] = make_float4(0.f, 0.f, 0.f, 0.f);
    }
}
template<int HALF>
__device__ __forceinline__ void sts_A_half(const float4 av[4], char* sm, uint32_t stOff,
                                           int tid) {
#pragma unroll
    for (int i = 2 * HALF; i < 2 * HALF + 2; ++i) {
        int j = tid + i * NTHREADS;
        int r = j >> 4, q = j & 15;
        float4 x = av[i];
        __nv_bfloat16 h0 = __float2bfloat16(x.x), h1 = __float2bfloat16(x.y);
        __nv_bfloat16 h2 = __float2bfloat16(x.z), h3 = __float2bfloat16(x.w);
        uint2 hp, lp;
        hp.x = pk(h0, h1); hp.y = pk(h2, h3);
        lp.x = pk(__float2bfloat16(x.x - __bfloat162float(h0)),
                  __float2bfloat16(x.y - __bfloat162float(h1)));
        lp.y = pk(__float2bfloat16(x.z - __bfloat162float(h2)),
                  __float2bfloat16(x.w - __bfloat162float(h3)));
        *(uint2*)(sm + stOff + SOFF_AH + r * RSTRIDE + q * 8) = hp;
        *(uint2*)(sm + stOff + SOFF_AL + r * RSTRIDE + q * 8) = lp;
    }
}

// ============================================================================
// Fragment load + MMA (32x32 warp tile)
// ============================================================================
__device__ __forceinline__ void ldsm_step(uint32_t st, int ks, Frag& f,
                                          const uint32_t aOff[2], const uint32_t bOff[2]) {
#pragma unroll
    for (int mt = 0; mt < 2; ++mt) {
        ldsm4(f.ah[mt][0], f.ah[mt][1], f.ah[mt][2], f.ah[mt][3], st + aOff[mt] + ks * 32);
        ldsm4(f.al[mt][0], f.al[mt][1], f.al[mt][2], f.al[mt][3],
              st + aOff[mt] + PLANE_BYTES + ks * 32);
    }
#pragma unroll
    for (int ng = 0; ng < 2; ++ng) {
        ldsm4(f.bh[2 * ng][0], f.bh[2 * ng][1], f.bh[2 * ng + 1][0], f.bh[2 * ng + 1][1],
              st + bOff[ng] + ks * 32);
        ldsm4(f.bl[2 * ng][0], f.bl[2 * ng][1], f.bl[2 * ng + 1][0], f.bl[2 * ng + 1][1],
              st + bOff[ng] + PLANE_BYTES + ks * 32);
    }
}
__device__ __forceinline__ void mma_step(float acc[2][4][4], const Frag& f) {
#pragma unroll
    for (int mt = 0; mt < 2; ++mt)
#pragma unroll
        for (int nt = 0; nt < 4; ++nt) {
            mma16816(acc[mt][nt], f.ah[mt], f.bh[nt]);
            mma16816(acc[mt][nt], f.al[mt], f.bh[nt]);
            mma16816(acc[mt][nt], f.ah[mt], f.bl[nt]);
        }
}

// ============================================================================
// Main GEMM.  D[m,n] = sum_k A[m,k]*B[n,k]
//   SPLIT: write fp32 partials to Pout; else fused bias+silu+hi/lo split
// ============================================================================
template<bool AFP32, bool SPLIT>
__global__ void __launch_bounds__(NTHREADS, 1)
gemm_main(const float* __restrict__ Afp,
          const __nv_bfloat16* __restrict__ Ahg, const __nv_bfloat16* __restrict__ Alg,
          int nchA, int nchTot,
          const __nv_bfloat16* __restrict__ Bhg, const __nv_bfloat16* __restrict__ Blg,
          int ldb,
          const float* __restrict__ bias,
          __nv_bfloat16* __restrict__ Oh, __nv_bfloat16* __restrict__ Ol,
          float* __restrict__ Pout)
{
    extern __shared__ char sm[];
    const uint32_t sb = (uint32_t)__cvta_generic_to_shared(sm);
    const int tid = threadIdx.x;
    const int nblk = blockIdx.x;
    const int row0 = blockIdx.y * MT;
    const int s = row0 >> 13;               // 8192 atoms / species
    const int z = SPLIT ? blockIdx.z : 0;
    const int kbase = (SPLIT && z) ? nchA * KC : 0;
    const int nch = SPLIT ? (z ? nchTot - nchA : nchA) : nchA;
    const int Klim = AFP32 ? (N_FEAT - kbase) : 0x7fffffff;

    const __nv_bfloat16* Bh0 = Bhg + ((size_t)s * HIDDEN + nblk * NTILE) * ldb + kbase;
    const __nv_bfloat16* Bl0 = Blg + ((size_t)s * HIDDEN + nblk * NTILE) * ldb + kbase;
    const float* Abase = AFP32 ? (Afp + (size_t)row0 * N_FEAT + kbase) : nullptr;
    const __nv_bfloat16* Ah0 = AFP32 ? nullptr : (Ahg + (size_t)row0 * HIDDEN);
    const __nv_bfloat16* Al0 = AFP32 ? nullptr : (Alg + (size_t)row0 * HIDDEN);

    float* sbias = (float*)(sm + OFF_BIAS);
    if (!SPLIT && tid < NTILE) sbias[tid] = bias[s * HIDDEN + nblk * NTILE + tid];

    // ---- prologue: fill stages 0 and 1 (nch >= 2 always) ----
    float4 av[4];
    if (AFP32) { ldg_A_half<0>(av, Abase, 0, tid, Klim); ldg_A_half<1>(av, Abase, 0, tid, Klim); }
    cp_B_half<0>(sb, Bh0, Bl0, ldb, 0, tid);
    cp_B_half<1>(sb, Bh0, Bl0, ldb, 0, tid);
    if (!AFP32) { cp_A_half<0>(sb, Ah0, Al0, 0, tid); cp_A_half<1>(sb, Ah0, Al0, 0, tid); }
    cp_commit();
    cp_B_half<0>(sb + STAGE_BYTES, Bh0, Bl0, ldb, KC, tid);
    cp_B_half<1>(sb + STAGE_BYTES, Bh0, Bl0, ldb, KC, tid);
    if (!AFP32) {
        cp_A_half<0>(sb + STAGE_BYTES, Ah0, Al0, KC, tid);
        cp_A_half<1>(sb + STAGE_BYTES, Ah0, Al0, KC, tid);
    }
    cp_commit();
    if (AFP32) {
        sts_A_half<0>(av, sm, 0, tid);
        sts_A_half<1>(av, sm, 0, tid);
        ldg_A_half<0>(av, Abase, KC, tid, Klim);
        ldg_A_half<1>(av, Abase, KC, tid, Klim);
        sts_A_half<0>(av, sm, STAGE_BYTES, tid);
        sts_A_half<1>(av, sm, STAGE_BYTES, tid);
    }

    // ---- per-warp fragment addressing: 16 warps, 32x32 tiles (4x4 grid) ----
    const int lane = tid & 31, wid = tid >> 5;
    const int warpM = wid & 3, warpN = wid >> 2;
    const int m0 = warpM * 32, n0 = warpN * 32;
    const int lr = lane & 15, lcb = (lane >> 4) * 16;
    uint32_t aOff[2], bOff[2];
#pragma unroll
    for (int mt = 0; mt < 2; ++mt)
        aOff[mt] = SOFF_AH + (uint32_t)(m0 + mt * 16 + lr) * RSTRIDE + lcb;
    const int brow = (lane & 7) + ((lane & 16) >> 1);
    const int bcb = (lane & 8) * 2;
#pragma unroll
    for (int ng = 0; ng < 2; ++ng)
        bOff[ng] = SOFF_BH + (uint32_t)(n0 + ng * 16 + brow) * RSTRIDE + bcb;

    float acc[2][4][4];
#pragma unroll
    for (int mt = 0; mt < 2; ++mt)
#pragma unroll
        for (int nt = 0; nt < 4; ++nt)
#pragma unroll
            for (int q = 0; q < 4; ++q) acc[mt][nt][q] = 0.f;

    // ---- main loop: 3-stage ring, chores spread across k-steps ----
    Frag f;
    uint32_t st0 = 0, st1 = STAGE_BYTES, st2 = 2 * STAGE_BYTES;
    for (int c = 0; c < nch; ++c) {
        if (c + 1 < nch) { cp_wait<1>(); } else { cp_wait<0>(); }
        __syncthreads();
        const uint32_t cur = sb + st0;
        const bool pf = (c + 2 < nch);
        const int k2 = (c + 2) * KC;

        // ks0: + ldg half0 (chunk c+2)
        ldsm_step(cur, 0, f, aOff, bOff);
        if (AFP32 && pf) ldg_A_half<0>(av, Abase, k2, tid, Klim);
        mma_step(acc, f);

        // ks1: + ldg half1, cp_B half0 (stage c+2)
        ldsm_step(cur, 1, f, aOff, bOff);
        if (AFP32 && pf) ldg_A_half<1>(av, Abase, k2, tid, Klim);
        if (pf) {
            cp_B_half<0>(sb + st2, Bh0, Bl0, ldb, k2, tid);
            if (!AFP32) cp_A_half<0>(sb + st2, Ah0, Al0, k2, tid);
        }
        mma_step(acc, f);

        // ks2: + cp_B half1 + commit, sts half0 -> stage c+2
        ldsm_step(cur, 2, f, aOff, bOff);
        if (pf) {
            cp_B_half<1>(sb + st2, Bh0, Bl0, ldb, k2, tid);
            if (!AFP32) cp_A_half<1>(sb + st2, Ah0, Al0, k2, tid);
            cp_commit();
        }
        if (AFP32 && pf) sts_A_half<0>(av, sm, st2, tid);
        mma_step(acc, f);

        // ks3: + sts half1 -> stage c+2
        ldsm_step(cur, 3, f, aOff, bOff);
        if (AFP32 && pf) sts_A_half<1>(av, sm, st2, tid);
        mma_step(acc, f);

        uint32_t t = st0; st0 = st1; st1 = st2; st2 = t;
    }

    // ---- epilogue ----
    if (SPLIT) {
        float* P = Pout + (size_t)z * N_ATOMS * HIDDEN;
#pragma unroll
        for (int mt = 0; mt < 2; ++mt)
#pragma unroll
            for (int nt = 0; nt < 4; ++nt) {
                const int rg = row0 + m0 + mt * 16 + (lane >> 2);
                const int cg = nblk * NTILE + n0 + nt * 8 + (lane & 3) * 2;
                float2 v0 = make_float2(acc[mt][nt][0], acc[mt][nt][1]);
                float2 v1 = make_float2(acc[mt][nt][2], acc[mt][nt][3]);
                *(float2*)(P + (size_t)rg * HIDDEN + cg) = v0;
                *(float2*)(P + (size_t)(rg + 8) * HIDDEN + cg) = v1;
            }
    } else {
#pragma unroll
        for (int mt = 0; mt < 2; ++mt)
#pragma unroll
            for (int nt = 0; nt < 4; ++nt) {
                const int rg = row0 + m0 + mt * 16 + (lane >> 2);
                const int cl = n0 + nt * 8 + (lane & 3) * 2;
                const int cg = nblk * NTILE + cl;
                const float b0 = sbias[cl], b1 = sbias[cl + 1];
                float v[4];
                v[0] = acc[mt][nt][0] + b0; v[1] = acc[mt][nt][1] + b1;
                v[2] = acc[mt][nt][2] + b0; v[3] = acc[mt][nt][3] + b1;
#pragma unroll
                for (int q = 0; q < 4; ++q) v[q] = v[q] / (1.f + __expf(-v[q]));
                __nv_bfloat16 h0 = __float2bfloat16(v[0]), h1 = __float2bfloat16(v[1]);
                __nv_bfloat16 h2 = __float2bfloat16(v[2]), h3 = __float2bfloat16(v[3]);
                uint32_t hi0 = pk(h0, h1), hi1 = pk(h2, h3);
                uint32_t lo0 = pk(__float2bfloat16(v[0] - __bfloat162float(h0)),
                                  __float2bfloat16(v[1] - __bfloat162float(h1)));
                uint32_t lo1 = pk(__float2bfloat16(v[2] - __bfloat162float(h2)),
                                  __float2bfloat16(v[3] - __bfloat162float(h3)));
                *(uint32_t*)(Oh + (size_t)rg * HIDDEN + cg) = hi0;
                *(uint32_t*)(Ol + (size_t)rg * HIDDEN + cg) = lo0;
                *(uint32_t*)(Oh + (size_t)(rg + 8) * HIDDEN + cg) = hi1;
                *(uint32_t*)(Ol + (size_t)(rg + 8) * HIDDEN + cg) = lo1;
            }
    }
}

// ============================================================================
// Split-K combine: P0 + P1 + bias -> silu -> bf16 hi/lo planes
// ============================================================================
__global__ void __launch_bounds__(256)
combine_silu(const float* __restrict__ P, const float* __restrict__ bias,
             __nv_bfloat16* __restrict__ Oh, __nv_bfloat16* __restrict__ Ol)
{
    const size_t i4 = ((size_t)blockIdx.x * 256 + threadIdx.x) * 4;
    const int row = (int)(i4 >> 8);
    const int col = (int)(i4 & 255);
    const int s = row >> 13;
    float4 a = *(const float4*)(P + i4);
    float4 b = *(const float4*)(P + (size_t)N_ATOMS * HIDDEN + i4);
    const float* bp = bias + s * HIDDEN + col;
    float v[4] = {a.x + b.x + bp[0], a.y + b.y + bp[1],
                  a.z + b.z + bp[2], a.w + b.w + bp[3]};
#pragma unroll
    for (int q = 0; q < 4; ++q) v[q] = v[q] / (1.f + __expf(-v[q]));
    __nv_bfloat16 h0 = __float2bfloat16(v[0]), h1 = __float2bfloat16(v[1]);
    __nv_bfloat16 h2 = __float2bfloat16(v[2]), h3 = __float2bfloat16(v[3]);
    uint2 hp, lp;
    hp.x = pk(h0, h1); hp.y = pk(h2, h3);
    lp.x = pk(__float2bfloat16(v[0] - __bfloat162float(h0)),
              __float2bfloat16(v[1] - __bfloat162float(h1)));
    lp.y = pk(__float2bfloat16(v[2] - __bfloat162float(h2)),
              __float2bfloat16(v[3] - __bfloat162float(h3)));
    *(uint2*)(Oh + i4) = hp;
    *(uint2*)(Ol + i4) = lp;
}

// ============================================================================
// Weight transpose + bf16 hi/lo split:  W[s][f][h] -> Wt[s][h][fp]
// ============================================================================
__global__ void transpose_split(const float* __restrict__ W,
                                __nv_bfloat16* __restrict__ Th,
                                __nv_bfloat16* __restrict__ Tl,
                                int F, int Fp, int H)
{
    __shared__ float t[32][33];
    const int s = blockIdx.z;
    const int f0 = blockIdx.x * 32, h0 = blockIdx.y * 32;
    const float* Ws = W + (size_t)s * F * H;
#pragma unroll
    for (int i = threadIdx.y; i < 32; i += 8) {
        int f = f0 + i, h = h0 + threadIdx.x;
        t[i][threadIdx.x] = (f < F) ? Ws[(size_t)f * H + h] : 0.f;
    }
    __syncthreads();
    __nv_bfloat16* Ths = Th + (size_t)s * H * Fp;
    __nv_bfloat16* Tls = Tl + (size_t)s * H * Fp;
#pragma unroll
    for (int i = threadIdx.y; i < 32; i += 8) {
        int h = h0 + i, f = f0 + threadIdx.x;
        float v = t[threadIdx.x][i];
        __nv_bfloat16 hi = __float2bfloat16(v);
        float lo = v - __bfloat162float(hi);
        Ths[(size_t)h * Fp + f] = hi;
        Tls[(size_t)h * Fp + f] = __float2bfloat16(lo);
    }
}

// ============================================================================
// Output zero + final layer-4 dot + segment scatter-add
// ============================================================================
__global__ void zero_out(float* out, int n) {
    int i = blockIdx.x * blockDim.x + threadIdx.x;
    if (i < n) out[i] = 0.f;
}

__global__ void __launch_bounds__(256)
layer4_reduce(const __nv_bfloat16* __restrict__ Hh,
              const __nv_bfloat16* __restrict__ Hl,
              const float* __restrict__ W4, const float* __restrict__ b4,
              const int* __restrict__ sidx, float* __restrict__ out)
{
    __shared__ float w[HIDDEN];
    const int atom = blockIdx.x * 256 + threadIdx.x;
    const int s = atom >> 13;
    w[threadIdx.x] = W4[s * HIDDEN + threadIdx.x];
    __syncthreads();

    const uint4* ph = (const uint4*)(Hh + (size_t)atom * HIDDEN);
    const uint4* pl = (const uint4*)(Hl + (size_t)atom * HIDDEN);
    float e = b4[s];
#pragma unroll 8
    for (int i = 0; i < 32; ++i) {
        uint4 a = ph[i];
        uint4 c = pl[i];
        const uint32_t* ap = &a.x;
        const uint32_t* cp = &c.x;
#pragma unroll
        for (int j = 0; j < 4; ++j) {
            __nv_bfloat162 hv = *(__nv_bfloat162*)&ap[j];
            __nv_bfloat162 lv = *(__nv_bfloat162*)&cp[j];
            int col = i * 8 + j * 2;
            e += (__bfloat162float(hv.x) + __bfloat162float(lv.x)) * w[col];
            e += (__bfloat162float(hv.y) + __bfloat162float(lv.y)) * w[col + 1];
        }
    }
    atomicAdd(out + sidx[atom], e);
}

// ============================================================================
// Host launcher
// ============================================================================
extern "C" void kernel_launch(void* const* d_in, const int* in_sizes, int n_in,
                              void* d_out, int out_size)
{
    int o = 0;
    const float* feat = (const float*)d_in[o++];
    const int* sidx = (const int*)d_in[o++];
    if (o < n_in && in_sizes[o] == 1) o++;  // n_structures scalar, if present
    const float* W1 = (const float*)d_in[o++];
    const float* b1 = (const float*)d_in[o++];
    const float* W2 = (const float*)d_in[o++];
    const float* b2 = (const float*)d_in[o++];
    const float* W3 = (const float*)d_in[o++];
    const float* b3 = (const float*)d_in[o++];
    const float* W4 = (const float*)d_in[o++];
    const float* b4 = (const float*)d_in[o++];

    __nv_bfloat16 *w1h, *w1l, *w2h, *w2l, *w3h, *w3l, *h1h, *h1l, *h2h, *h2l;
    float* pbuf;
    cudaGetSymbolAddress((void**)&w1h, g_W1h);
    cudaGetSymbolAddress((void**)&w1l, g_W1l);
    cudaGetSymbolAddress((void**)&w2h, g_W2h);
    cudaGetSymbolAddress((void**)&w2l, g_W2l);
    cudaGetSymbolAddress((void**)&w3h, g_W3h);
    cudaGetSymbolAddress((void**)&w3l, g_W3l);
    cudaGetSymbolAddress((void**)&h1h, g_H1h);
    cudaGetSymbolAddress((void**)&h1l, g_H1l);
    cudaGetSymbolAddress((void**)&h2h, g_H2h);
    cudaGetSymbolAddress((void**)&h2l, g_H2l);
    cudaGetSymbolAddress((void**)&pbuf, g_P);

    cudaFuncSetAttribute(gemm_main<true, true>,
                         cudaFuncAttributeMaxDynamicSharedMemorySize, SMEM_DYN);
    cudaFuncSetAttribute(gemm_main<false, false>,
                         cudaFuncAttributeMaxDynamicSharedMemorySize, SMEM_DYN);

    // Prep: transpose + hi/lo split weights (K-major, zero-padded to N_FEAT_P)
    transpose_split<<<dim3(N_FEAT_P / 32, HIDDEN / 32, N_SPECIES), dim3(32, 8)>>>(
        W1, w1h, w1l, N_FEAT, N_FEAT_P, HIDDEN);
    transpose_split<<<dim3(HIDDEN / 32, HIDDEN / 32, N_SPECIES), dim3(32, 8)>>>(
        W2, w2h, w2l, HIDDEN, HIDDEN, HIDDEN);
    transpose_split<<<dim3(HIDDEN / 32, HIDDEN / 32, N_SPECIES), dim3(32, 8)>>>(
        W3, w3h, w3l, HIDDEN, HIDDEN, HIDDEN);

    // Layer 1: split-K x2 -> fp32 partials -> combine(bias+silu+split)
    gemm_main<true, true><<<dim3(HIDDEN / NTILE, N_ATOMS / MT, 2), NTHREADS, SMEM_DYN>>>(
        feat, nullptr, nullptr, NCH0, TOTCH,
        w1h, w1l, N_FEAT_P, nullptr, nullptr, nullptr, pbuf);
    combine_silu<<<(N_ATOMS * HIDDEN) / (256 * 4), 256>>>(pbuf, b1, h1h, h1l);

    const dim3 grid2(HIDDEN / NTILE, N_ATOMS / MT);

    // Layer 2: A = H1 planes (K = 256, 4 chunks)
    gemm_main<false, false><<<grid2, NTHREADS, SMEM_DYN>>>(
        nullptr, h1h, h1l, HIDDEN / KC, HIDDEN / KC,
        w2h, w2l, HIDDEN, b2, h2h, h2l, nullptr);

    // Layer 3: A = H2 planes -> H1
    gemm_main<false, false><<<grid2, NTHREADS, SMEM_DYN>>>(
        nullptr, h2h, h2l, HIDDEN / KC, HIDDEN / KC,
        w3h, w3l, HIDDEN, b3, h1h, h1l, nullptr);

    // Layer 4 + segment sum
    zero_out<<<(out_size + 255) / 256, 256>>>((float*)d_out, out_size);
    layer4_reduce<<<N_ATOMS / 256, 256>>>(h1h, h1l, W4, b4, sidx, (float*)d_out);
}